// round 7
// baseline (speedup 1.0000x reference)
#include <cuda_runtime.h>

#define OUT_H      8
#define MAX_WIDTH  384
#define FH         160
#define FW         160
#define CCH        32
#define NUM_BOXES  256
#define NF4        (MAX_WIDTH * (CCH / 4))   // 3072 float4 per (box,row) strip

// One block per (box,row) strip of 384 pixels.
// Phase 1: per-pixel bilinear weights + corner indices computed ONCE into smem.
// Phase 2: stream 3072 float4 outputs; invalid pixels (col >= bw) skip the
// smem reads and all four gathers entirely (only a zero store issues).

__global__ __launch_bounds__(256)
void rotate_bilinear_kernel(const float* __restrict__ feat,
                            const float* __restrict__ theta,
                            const int*   __restrict__ box_info,
                            float4*      __restrict__ out)
{
    __shared__ float4 sw[MAX_WIDTH];   // wa, wb, wc, wd
    __shared__ int4   si[MAX_WIDTH];   // float4-unit base indices of 4 corners

    const int t   = blockIdx.x;        // b*OUT_H + row
    const int b   = t >> 3;
    const int row = t & (OUT_H - 1);
    const int tid = threadIdx.x;

    const int bw = __ldg(&box_info[2 * b + 1]);

    // ---- Phase 1: per-pixel weights + indices (once per pixel) ----
    if (tid < 128 || tid + 128 < MAX_WIDTH || true) {
        const int img = __ldg(&box_info[2 * b]);
        const float* th = theta + 6 * b;
        const float t0 = __ldg(th + 0), t1 = __ldg(th + 1), t2 = __ldg(th + 2);
        const float t3 = __ldg(th + 3), t4 = __ldg(th + 4), t5 = __ldg(th + 5);

        const float rcp2 = __fdividef(2.0f, (float)bw - 1.0f);
        const float yt   = -1.0f + 2.0f * (float)row * (1.0f / (float)(OUT_H - 1));

        // x = Ax*p + Bx, y = Ay*p + By  (fold of the affine transform)
        const float Ax = t0 * rcp2 * ((float)FW * 0.5f);
        const float Bx = (t1 * yt + t2 - t0 + 1.0f) * ((float)FW * 0.5f);
        const float Ay = t3 * rcp2 * ((float)FH * 0.5f);
        const float By = (t4 * yt + t5 - t3 + 1.0f) * ((float)FH * 0.5f);

        for (int p = tid; p < MAX_WIDTH; p += 256) {
            float4 w  = make_float4(0.f, 0.f, 0.f, 0.f);
            int4   ii = make_int4(0, 0, 0, 0);
            if (p < bw) {
                const float pf = (float)p;
                const float x  = fmaf(Ax, pf, Bx);
                const float y  = fmaf(Ay, pf, By);
                const int x0i = __float2int_rd(x);
                const int y0i = __float2int_rd(y);
                const int x0c = min(max(x0i,     0), FW - 1);
                const int x1c = min(max(x0i + 1, 0), FW - 1);
                const int y0c = min(max(y0i,     0), FH - 1);
                const int y1c = min(max(y0i + 1, 0), FH - 1);
                const float dx0 = (float)x1c - x, dx1 = x - (float)x0c;
                const float dy0 = (float)y1c - y, dy1 = y - (float)y0c;
                w = make_float4(dx0 * dy0, dx0 * dy1, dx1 * dy0, dx1 * dy1);
                const int rA = (img * FH + y0c) * FW;
                const int rB = (img * FH + y1c) * FW;
                ii = make_int4((rA + x0c) * (CCH / 4),
                               (rB + x0c) * (CCH / 4),
                               (rA + x1c) * (CCH / 4),
                               (rB + x1c) * (CCH / 4));
            }
            sw[p] = w;
            si[p] = ii;
        }
    }
    __syncthreads();

    // ---- Phase 2: stream 3072 float4 outputs; skip gathers for invalid ----
    const float4* __restrict__ f4 = (const float4*)feat;
    float4* __restrict__ ob = out + (long)t * NF4;

    #pragma unroll 4
    for (int it = 0; it < NF4 / 256; ++it) {
        const int idx = it * 256 + tid;
        const int p   = idx >> 3;          // pixel (column)
        const int c4  = idx & 7;           // float4 slot within 32 channels

        float4 o = make_float4(0.f, 0.f, 0.f, 0.f);

        if (p < bw) {
            const float4 w  = sw[p];
            const int4   ii = si[p];

            const float4 Ia = __ldg(f4 + ii.x + c4);
            const float4 Ib = __ldg(f4 + ii.y + c4);
            const float4 Ic = __ldg(f4 + ii.z + c4);
            const float4 Id = __ldg(f4 + ii.w + c4);

            o.x = w.x * Ia.x + w.y * Ib.x + w.z * Ic.x + w.w * Id.x;
            o.y = w.x * Ia.y + w.y * Ib.y + w.z * Ic.y + w.w * Id.y;
            o.z = w.x * Ia.z + w.y * Ib.z + w.z * Ic.z + w.w * Id.z;
            o.w = w.x * Ia.w + w.y * Ib.w + w.z * Ic.w + w.w * Id.w;
        }

        __stcs(ob + idx, o);
    }
}

extern "C" void kernel_launch(void* const* d_in, const int* in_sizes, int n_in,
                              void* d_out, int out_size)
{
    const float* feat  = (const float*)d_in[0];   // [8,160,160,32] f32
    const float* theta = (const float*)d_in[1];   // [256,6] f32
    const int*   binfo = (const int*)d_in[2];     // [256,2] i32

    const int grid = NUM_BOXES * OUT_H;           // 2048 blocks
    rotate_bilinear_kernel<<<grid, 256>>>(feat, theta, binfo, (float4*)d_out);
}

// round 8
// speedup vs baseline: 1.0012x; 1.0012x over previous
#include <cuda_runtime.h>

#define OUT_H      8
#define MAX_WIDTH  384
#define QW         96            // MAX_WIDTH / 4
#define FH         160
#define FW         160
#define CCH        32
#define NUM_BOXES  256

// 8 threads per pixel (one float4 each -> 128B-contiguous gathers).
// Each thread handles 4 pixels (cols c, c+96, c+192, c+288), processed in
// two batches of 2 so 8 gathers are in flight at once. Accumulation uses
// packed fma.rn.f32x2.

__device__ __forceinline__ unsigned long long pk2(float a, float b) {
    unsigned long long r;
    asm("mov.b64 %0, {%1, %2};" : "=l"(r) : "f"(a), "f"(b));
    return r;
}
__device__ __forceinline__ unsigned long long mul2(unsigned long long a, unsigned long long b) {
    unsigned long long d;
    asm("mul.rn.f32x2 %0, %1, %2;" : "=l"(d) : "l"(a), "l"(b));
    return d;
}
__device__ __forceinline__ unsigned long long fma2(unsigned long long a, unsigned long long b, unsigned long long c) {
    unsigned long long d;
    asm("fma.rn.f32x2 %0, %1, %2, %3;" : "=l"(d) : "l"(a), "l"(b), "l"(c));
    return d;
}
__device__ __forceinline__ float4 unpk4(unsigned long long lo, unsigned long long hi) {
    float4 o;
    asm("mov.b64 {%0, %1}, %2;" : "=f"(o.x), "=f"(o.y) : "l"(lo));
    asm("mov.b64 {%0, %1}, %2;" : "=f"(o.z), "=f"(o.w) : "l"(hi));
    return o;
}

struct Px {
    float wa, wb, wc, wd;
    int ia, ib, ic, id;
};

__device__ __forceinline__ Px pixel_setup(int pc, float Ax, float Bx,
                                          float Ay, float By, int imgbase, int c4)
{
    Px r;
    const float pf = (float)pc;
    const float x  = fmaf(Ax, pf, Bx);
    const float y  = fmaf(Ay, pf, By);
    const int x0i = __float2int_rd(x);
    const int y0i = __float2int_rd(y);
    const int x0c = min(max(x0i,     0), FW - 1);
    const int x1c = min(max(x0i + 1, 0), FW - 1);
    const int y0c = min(max(y0i,     0), FH - 1);
    const int y1c = min(max(y0i + 1, 0), FH - 1);
    const float dx0 = (float)x1c - x, dx1 = x - (float)x0c;
    const float dy0 = (float)y1c - y, dy1 = y - (float)y0c;
    r.wa = dx0 * dy0; r.wb = dx0 * dy1; r.wc = dx1 * dy0; r.wd = dx1 * dy1;
    const int rA = (imgbase + y0c) * FW;
    const int rB = (imgbase + y1c) * FW;
    r.ia = (rA + x0c) * (CCH / 4) + c4;
    r.ib = (rB + x0c) * (CCH / 4) + c4;
    r.ic = (rA + x1c) * (CCH / 4) + c4;
    r.id = (rB + x1c) * (CCH / 4) + c4;
    return r;
}

__device__ __forceinline__ float4 pixel_blend(const Px& px,
                                              float4 Ia, float4 Ib,
                                              float4 Ic, float4 Id)
{
    const unsigned long long wa2 = pk2(px.wa, px.wa);
    const unsigned long long wb2 = pk2(px.wb, px.wb);
    const unsigned long long wc2 = pk2(px.wc, px.wc);
    const unsigned long long wd2 = pk2(px.wd, px.wd);

    unsigned long long o01 = mul2(wa2, pk2(Ia.x, Ia.y));
    unsigned long long o23 = mul2(wa2, pk2(Ia.z, Ia.w));
    o01 = fma2(wb2, pk2(Ib.x, Ib.y), o01);
    o23 = fma2(wb2, pk2(Ib.z, Ib.w), o23);
    o01 = fma2(wc2, pk2(Ic.x, Ic.y), o01);
    o23 = fma2(wc2, pk2(Ic.z, Ic.w), o23);
    o01 = fma2(wd2, pk2(Id.x, Id.y), o01);
    o23 = fma2(wd2, pk2(Id.z, Id.w), o23);
    return unpk4(o01, o23);
}

__global__ __launch_bounds__(256)
void rotate_bilinear_kernel(const float* __restrict__ feat,
                            const float* __restrict__ theta,
                            const int*   __restrict__ box_info,
                            float4*      __restrict__ out)
{
    const int tid = blockIdx.x * blockDim.x + threadIdx.x;

    const int c4  = tid & 7;
    const int p   = tid >> 3;
    const int col = p % QW;
    const int t   = p / QW;
    const int row = t & (OUT_H - 1);
    const int b   = t >> 3;

    const int img = __ldg(&box_info[2 * b]);
    const int bw  = __ldg(&box_info[2 * b + 1]);

    const float* th = theta + 6 * b;
    const float t0 = __ldg(th + 0), t1 = __ldg(th + 1), t2 = __ldg(th + 2);
    const float t3 = __ldg(th + 3), t4 = __ldg(th + 4), t5 = __ldg(th + 5);

    const float rcp2 = __fdividef(2.0f, (float)bw - 1.0f);
    const float yt   = -1.0f + 2.0f * (float)row * (1.0f / (float)(OUT_H - 1));

    const float Ax = t0 * rcp2 * ((float)FW * 0.5f);
    const float Bx = (t1 * yt + t2 - t0 + 1.0f) * ((float)FW * 0.5f);
    const float Ay = t3 * rcp2 * ((float)FH * 0.5f);
    const float By = (t4 * yt + t5 - t3 + 1.0f) * ((float)FH * 0.5f);
    const int imgbase = img * FH;

    const float4* __restrict__ f4 = (const float4*)feat;
    const long opix = (long)(t * MAX_WIDTH + col);

    #pragma unroll
    for (int kk = 0; kk < 4; kk += 2) {
        const int pc0 = col + kk * QW;
        const int pc1 = pc0 + QW;
        const bool v0 = (pc0 < bw);
        const bool v1 = (pc1 < bw);

        // Index/weight math (finite for any pc, compute unconditionally)
        const Px px0 = pixel_setup(pc0, Ax, Bx, Ay, By, imgbase, c4);
        const Px px1 = pixel_setup(pc1, Ax, Bx, Ay, By, imgbase, c4);

        float4 Ia0 = {0,0,0,0}, Ib0 = {0,0,0,0}, Ic0 = {0,0,0,0}, Id0 = {0,0,0,0};
        float4 Ia1 = {0,0,0,0}, Ib1 = {0,0,0,0}, Ic1 = {0,0,0,0}, Id1 = {0,0,0,0};

        // Issue both pixels' gathers back-to-back: 8 loads in flight
        if (v0) {
            Ia0 = __ldg(f4 + px0.ia); Ib0 = __ldg(f4 + px0.ib);
            Ic0 = __ldg(f4 + px0.ic); Id0 = __ldg(f4 + px0.id);
        }
        if (v1) {
            Ia1 = __ldg(f4 + px1.ia); Ib1 = __ldg(f4 + px1.ib);
            Ic1 = __ldg(f4 + px1.ic); Id1 = __ldg(f4 + px1.id);
        }

        float4 o0 = make_float4(0.f, 0.f, 0.f, 0.f);
        float4 o1 = o0;
        if (v0) o0 = pixel_blend(px0, Ia0, Ib0, Ic0, Id0);
        if (v1) o1 = pixel_blend(px1, Ia1, Ib1, Ic1, Id1);

        __stcs(out + (opix + (long)kk * QW)       * (CCH / 4) + c4, o0);
        __stcs(out + (opix + (long)(kk + 1) * QW) * (CCH / 4) + c4, o1);
    }
}

extern "C" void kernel_launch(void* const* d_in, const int* in_sizes, int n_in,
                              void* d_out, int out_size)
{
    const float* feat  = (const float*)d_in[0];   // [8,160,160,32] f32
    const float* theta = (const float*)d_in[1];   // [256,6] f32
    const int*   binfo = (const int*)d_in[2];     // [256,2] i32

    const int total_threads = NUM_BOXES * OUT_H * QW * 8; // 1,572,864
    const int block = 256;
    const int grid  = total_threads / block;      // 6144

    rotate_bilinear_kernel<<<grid, block>>>(feat, theta, binfo, (float4*)d_out);
}

// round 9
// speedup vs baseline: 1.0626x; 1.0613x over previous
#include <cuda_runtime.h>

#define OUT_H      8
#define MAX_WIDTH  384
#define PBW        96            // pixel-blocks per strip (4 consecutive cols each)
#define FH         160
#define FW         160
#define CCH        32
#define NUM_BOXES  256

// 8 threads per pixel (one float4 each -> 128B-contiguous gathers, 4 L1
// wavefronts per warp LDG). Each thread owns FOUR CONSECUTIVE columns
// (col0..col0+3), so a warp covers a 16-column window of one (box,row) strip
// (24 warps tile a strip exactly). Warps whose window is entirely beyond the
// box width store zeros and exit -- ~half of all warps skip all math/gathers.

__global__ __launch_bounds__(256)
void rotate_bilinear_kernel(const float* __restrict__ feat,
                            const float* __restrict__ theta,
                            const int*   __restrict__ box_info,
                            float4*      __restrict__ out)
{
    const int tid = blockIdx.x * blockDim.x + threadIdx.x;

    const int c4  = tid & 7;          // float4 slot within 32 channels
    const int pb  = tid >> 3;         // pixel-block id
    const int pbs = pb % PBW;         // pixel-block within strip
    const int t   = pb / PBW;         // strip = b*OUT_H + row
    const int col0 = pbs * 4;         // first of 4 consecutive columns
    const int row = t & (OUT_H - 1);
    const int b   = t >> 3;

    const int bw = __ldg(&box_info[2 * b + 1]);

    // Output base for this thread's first pixel (float4 units)
    float4* __restrict__ op = out + ((long)t * MAX_WIDTH + col0) * (CCH / 4) + c4;

    // Warp-uniform early-out: warp's smallest column
    const int warp_col_min = ((pb & ~3) % PBW) * 4;   // lane0's col0 (uniform)
    if (warp_col_min >= bw) {
        const float4 z = make_float4(0.f, 0.f, 0.f, 0.f);
        __stcs(op,                  z);
        __stcs(op + 1 * (CCH / 4), z);
        __stcs(op + 2 * (CCH / 4), z);
        __stcs(op + 3 * (CCH / 4), z);
        return;
    }

    const int img = __ldg(&box_info[2 * b]);
    const float* th = theta + 6 * b;
    const float t0 = __ldg(th + 0), t1 = __ldg(th + 1), t2 = __ldg(th + 2);
    const float t3 = __ldg(th + 3), t4 = __ldg(th + 4), t5 = __ldg(th + 5);

    const float rcp2 = __fdividef(2.0f, (float)bw - 1.0f);
    const float yt   = -1.0f + 2.0f * (float)row * (1.0f / (float)(OUT_H - 1));

    // Folded transform: x = Ax*col + Bx, y = Ay*col + By
    const float Ax = t0 * rcp2 * ((float)FW * 0.5f);
    const float Bx = (t1 * yt + t2 - t0 + 1.0f) * ((float)FW * 0.5f);
    const float Ay = t3 * rcp2 * ((float)FH * 0.5f);
    const float By = (t4 * yt + t5 - t3 + 1.0f) * ((float)FH * 0.5f);
    const int imgbase = img * FH;

    const float4* __restrict__ f4 = (const float4*)feat;

    #pragma unroll
    for (int k = 0; k < 4; ++k) {
        const int pc = col0 + k;
        float4 o = make_float4(0.f, 0.f, 0.f, 0.f);

        if (pc < bw) {
            const float pf = (float)pc;
            const float x  = fmaf(Ax, pf, Bx);
            const float y  = fmaf(Ay, pf, By);

            const int x0i = __float2int_rd(x);
            const int y0i = __float2int_rd(y);
            const int x0c = min(max(x0i,     0), FW - 1);
            const int x1c = min(max(x0i + 1, 0), FW - 1);
            const int y0c = min(max(y0i,     0), FH - 1);
            const int y1c = min(max(y0i + 1, 0), FH - 1);

            const float dx0 = (float)x1c - x, dx1 = x - (float)x0c;
            const float dy0 = (float)y1c - y, dy1 = y - (float)y0c;
            const float wa = dx0 * dy0, wb = dx0 * dy1;
            const float wc = dx1 * dy0, wd = dx1 * dy1;

            const int rA = (imgbase + y0c) * FW;
            const int rB = (imgbase + y1c) * FW;

            const float4 Ia = __ldg(f4 + (rA + x0c) * (CCH / 4) + c4);
            const float4 Ib = __ldg(f4 + (rB + x0c) * (CCH / 4) + c4);
            const float4 Ic = __ldg(f4 + (rA + x1c) * (CCH / 4) + c4);
            const float4 Id = __ldg(f4 + (rB + x1c) * (CCH / 4) + c4);

            o.x = wa * Ia.x + wb * Ib.x + wc * Ic.x + wd * Id.x;
            o.y = wa * Ia.y + wb * Ib.y + wc * Ic.y + wd * Id.y;
            o.z = wa * Ia.z + wb * Ib.z + wc * Ic.z + wd * Id.z;
            o.w = wa * Ia.w + wb * Ib.w + wc * Ic.w + wd * Id.w;
        }

        __stcs(op + k * (CCH / 4), o);
    }
}

extern "C" void kernel_launch(void* const* d_in, const int* in_sizes, int n_in,
                              void* d_out, int out_size)
{
    const float* feat  = (const float*)d_in[0];   // [8,160,160,32] f32
    const float* theta = (const float*)d_in[1];   // [256,6] f32
    const int*   binfo = (const int*)d_in[2];     // [256,2] i32

    const int total_threads = NUM_BOXES * OUT_H * PBW * 8; // 1,572,864
    const int block = 256;
    const int grid  = total_threads / block;      // 6144

    rotate_bilinear_kernel<<<grid, block>>>(feat, theta, binfo, (float4*)d_out);
}

// round 10
// speedup vs baseline: 1.0680x; 1.0051x over previous
#include <cuda_runtime.h>

#define OUT_H      8
#define MAX_WIDTH  384
#define EW         48            // MAX_WIDTH / 8 : column stride between a thread's pixels
#define FH         160
#define FW         160
#define CCH        32
#define NUM_BOXES  256

// 8 threads per pixel (one float4 each -> 128B-contiguous gathers, 4 L1
// wavefronts per warp LDG/STG). Each thread handles EIGHT pixels of the same
// (box,row): cols c + k*48, k=0..7. Preamble and addressing amortized 8x.

__global__ __launch_bounds__(256)
void rotate_bilinear_kernel(const float* __restrict__ feat,
                            const float* __restrict__ theta,
                            const int*   __restrict__ box_info,
                            float4*      __restrict__ out)
{
    const int tid = blockIdx.x * blockDim.x + threadIdx.x;

    const int c4  = tid & 7;          // float4 slot within 32 channels
    const int p   = tid >> 3;         // (box, row, col-slot)
    const int col = p % EW;           // base column; pixels at col + k*48
    const int t   = p / EW;           // strip = b*OUT_H + row
    const int row = t & (OUT_H - 1);
    const int b   = t >> 3;           // OUT_H == 8

    const int img = __ldg(&box_info[2 * b]);
    const int bw  = __ldg(&box_info[2 * b + 1]);

    const float* th = theta + 6 * b;
    const float t0 = __ldg(th + 0), t1 = __ldg(th + 1), t2 = __ldg(th + 2);
    const float t3 = __ldg(th + 3), t4 = __ldg(th + 4), t5 = __ldg(th + 5);

    const float rcp2 = __fdividef(2.0f, (float)bw - 1.0f);
    const float yt   = -1.0f + 2.0f * (float)row * (1.0f / (float)(OUT_H - 1));

    // Folded transform: x = Ax*col + Bx, y = Ay*col + By
    const float Ax = t0 * rcp2 * ((float)FW * 0.5f);
    const float Bx = (t1 * yt + t2 - t0 + 1.0f) * ((float)FW * 0.5f);
    const float Ay = t3 * rcp2 * ((float)FH * 0.5f);
    const float By = (t4 * yt + t5 - t3 + 1.0f) * ((float)FH * 0.5f);

    // Per-thread feature base with c4 folded in (float4 units)
    const float4* __restrict__ fb = (const float4*)feat + (long)img * (FH * FW * (CCH / 4)) + c4;

    // Per-thread output base (float4 units), pixels step by EW*(CCH/4)
    float4* __restrict__ op = out + ((long)t * MAX_WIDTH + col) * (CCH / 4) + c4;

    #pragma unroll
    for (int k = 0; k < 8; ++k) {
        const int pc = col + k * EW;
        float4 o = make_float4(0.f, 0.f, 0.f, 0.f);

        if (pc < bw) {
            const float pf = (float)pc;
            const float x  = fmaf(Ax, pf, Bx);
            const float y  = fmaf(Ay, pf, By);

            const int x0i = __float2int_rd(x);
            const int y0i = __float2int_rd(y);
            const int x0c = min(max(x0i,     0), FW - 1);
            const int x1c = min(max(x0i + 1, 0), FW - 1);
            const int y0c = min(max(y0i,     0), FH - 1);
            const int y1c = min(max(y0i + 1, 0), FH - 1);

            const float dx0 = (float)x1c - x, dx1 = x - (float)x0c;
            const float dy0 = (float)y1c - y, dy1 = y - (float)y0c;
            const float wa = dx0 * dy0, wb = dx0 * dy1;
            const float wc = dx1 * dy0, wd = dx1 * dy1;

            // float4-unit offsets within the image
            const int ry0 = y0c * (FW * (CCH / 4));
            const int ry1 = y1c * (FW * (CCH / 4));
            const int cx0 = x0c * (CCH / 4);
            const int cx1 = x1c * (CCH / 4);

            const float4 Ia = __ldg(fb + (ry0 + cx0));
            const float4 Ib = __ldg(fb + (ry1 + cx0));
            const float4 Ic = __ldg(fb + (ry0 + cx1));
            const float4 Id = __ldg(fb + (ry1 + cx1));

            o.x = wa * Ia.x + wb * Ib.x + wc * Ic.x + wd * Id.x;
            o.y = wa * Ia.y + wb * Ib.y + wc * Ic.y + wd * Id.y;
            o.z = wa * Ia.z + wb * Ib.z + wc * Ic.z + wd * Id.z;
            o.w = wa * Ia.w + wb * Ib.w + wc * Ic.w + wd * Id.w;
        }

        __stcs(op + k * (EW * (CCH / 4)), o);
    }
}

extern "C" void kernel_launch(void* const* d_in, const int* in_sizes, int n_in,
                              void* d_out, int out_size)
{
    const float* feat  = (const float*)d_in[0];   // [8,160,160,32] f32
    const float* theta = (const float*)d_in[1];   // [256,6] f32
    const int*   binfo = (const int*)d_in[2];     // [256,2] i32

    const int total_threads = NUM_BOXES * OUT_H * EW * 8; // 786,432
    const int block = 256;
    const int grid  = total_threads / block;      // 3072

    rotate_bilinear_kernel<<<grid, block>>>(feat, theta, binfo, (float4*)d_out);
}

// round 11
// speedup vs baseline: 1.0847x; 1.0156x over previous
#include <cuda_runtime.h>

#define OUT_H      8
#define MAX_WIDTH  384
#define QW         96            // MAX_WIDTH / 4
#define FH         160
#define FW         160
#define CCH        32
#define NUM_BOXES  256

// R5 layout: 8 threads per pixel (one float4 each -> 128B-contiguous gathers),
// 4 pixels per thread (cols c + k*96). NEW: depth-1 software pipeline -- the
// gathers for pixel k+1 are issued before pixel k's blend consumes its data,
// doubling memory-level parallelism per warp.

struct PxS { float wa, wb, wc, wd; int ia, ib, ic, id; };

__device__ __forceinline__ PxS px_setup(int pc, float Ax, float Bx,
                                        float Ay, float By)
{
    PxS r;
    const float pf = (float)pc;
    const float x  = fmaf(Ax, pf, Bx);
    const float y  = fmaf(Ay, pf, By);
    const int x0i = __float2int_rd(x);
    const int y0i = __float2int_rd(y);
    const int x0c = min(max(x0i,     0), FW - 1);
    const int x1c = min(max(x0i + 1, 0), FW - 1);
    const int y0c = min(max(y0i,     0), FH - 1);
    const int y1c = min(max(y0i + 1, 0), FH - 1);
    const float dx0 = (float)x1c - x, dx1 = x - (float)x0c;
    const float dy0 = (float)y1c - y, dy1 = y - (float)y0c;
    r.wa = dx0 * dy0; r.wb = dx0 * dy1; r.wc = dx1 * dy0; r.wd = dx1 * dy1;
    const int ry0 = y0c * (FW * (CCH / 4));
    const int ry1 = y1c * (FW * (CCH / 4));
    const int cx0 = x0c * (CCH / 4);
    const int cx1 = x1c * (CCH / 4);
    r.ia = ry0 + cx0; r.ib = ry1 + cx0; r.ic = ry0 + cx1; r.id = ry1 + cx1;
    return r;
}

__global__ __launch_bounds__(128)
void rotate_bilinear_kernel(const float* __restrict__ feat,
                            const float* __restrict__ theta,
                            const int*   __restrict__ box_info,
                            float4*      __restrict__ out)
{
    const int tid = blockIdx.x * blockDim.x + threadIdx.x;

    const int c4  = tid & 7;          // float4 slot within 32 channels
    const int p   = tid >> 3;         // (box, row, col-slot)
    const int col = p % QW;           // base column; pixels at col + k*96
    const int t   = p / QW;           // strip = b*OUT_H + row
    const int row = t & (OUT_H - 1);
    const int b   = t >> 3;           // OUT_H == 8

    const int img = __ldg(&box_info[2 * b]);
    const int bw  = __ldg(&box_info[2 * b + 1]);

    const float* th = theta + 6 * b;
    const float t0 = __ldg(th + 0), t1 = __ldg(th + 1), t2 = __ldg(th + 2);
    const float t3 = __ldg(th + 3), t4 = __ldg(th + 4), t5 = __ldg(th + 5);

    const float rcp2 = __fdividef(2.0f, (float)bw - 1.0f);
    const float yt   = -1.0f + 2.0f * (float)row * (1.0f / (float)(OUT_H - 1));

    const float Ax = t0 * rcp2 * ((float)FW * 0.5f);
    const float Bx = (t1 * yt + t2 - t0 + 1.0f) * ((float)FW * 0.5f);
    const float Ay = t3 * rcp2 * ((float)FH * 0.5f);
    const float By = (t4 * yt + t5 - t3 + 1.0f) * ((float)FH * 0.5f);

    // Feature base with image and channel-slot folded in (float4 units)
    const float4* __restrict__ fb =
        (const float4*)feat + (long)img * (FH * FW * (CCH / 4)) + c4;

    // Output base; pixels step by QW*(CCH/4)
    float4* __restrict__ op = out + ((long)t * MAX_WIDTH + col) * (CCH / 4) + c4;

    const float4 zero = make_float4(0.f, 0.f, 0.f, 0.f);

    // ---- pipeline prologue: pixel 0 setup + loads ----
    bool v = (col < bw);
    PxS  s = {};
    float4 A = zero, B = zero, C = zero, D = zero;
    if (v) {
        s = px_setup(col, Ax, Bx, Ay, By);
        A = __ldg(fb + s.ia);
        B = __ldg(fb + s.ib);
        C = __ldg(fb + s.ic);
        D = __ldg(fb + s.id);
    }

    #pragma unroll
    for (int k = 0; k < 4; ++k) {
        // ---- prefetch pixel k+1 (issued before blend consumes k's data) ----
        bool nv = false;
        PxS  ns = {};
        float4 nA = zero, nB = zero, nC = zero, nD = zero;
        if (k < 3) {
            const int npc = col + (k + 1) * QW;
            nv = (npc < bw);
            if (nv) {
                ns = px_setup(npc, Ax, Bx, Ay, By);
                nA = __ldg(fb + ns.ia);
                nB = __ldg(fb + ns.ib);
                nC = __ldg(fb + ns.ic);
                nD = __ldg(fb + ns.id);
            }
        }

        // ---- blend + store pixel k ----
        float4 o = zero;
        if (v) {
            o.x = s.wa * A.x + s.wb * B.x + s.wc * C.x + s.wd * D.x;
            o.y = s.wa * A.y + s.wb * B.y + s.wc * C.y + s.wd * D.y;
            o.z = s.wa * A.z + s.wb * B.z + s.wc * C.z + s.wd * D.z;
            o.w = s.wa * A.w + s.wb * B.w + s.wc * C.w + s.wd * D.w;
        }
        __stcs(op + k * (QW * (CCH / 4)), o);

        // ---- rotate ----
        v = nv; s = ns;
        A = nA; B = nB; C = nC; D = nD;
    }
}

extern "C" void kernel_launch(void* const* d_in, const int* in_sizes, int n_in,
                              void* d_out, int out_size)
{
    const float* feat  = (const float*)d_in[0];   // [8,160,160,32] f32
    const float* theta = (const float*)d_in[1];   // [256,6] f32
    const int*   binfo = (const int*)d_in[2];     // [256,2] i32

    const int total_threads = NUM_BOXES * OUT_H * QW * 8; // 1,572,864
    const int block = 128;
    const int grid  = total_threads / block;      // 12288

    rotate_bilinear_kernel<<<grid, block>>>(feat, theta, binfo, (float4*)d_out);
}